// round 1
// baseline (speedup 1.0000x reference)
#include <cuda_runtime.h>

// Problem constants
#define I_LEN 2048
#define J_LEN 2048
#define MDIM  1024
#define NHEAD 64     // "head" axis (weights dim1)
#define HD    16     // per-head contracted feature dim (weights dim2)

// ---------------- scratch (static device globals; no allocation) ----------------
__device__ float g_wq[I_LEN * MDIM];
__device__ float g_wk[J_LEN * MDIM];
__device__ float g_wv[J_LEN * MDIM];
__device__ float g_vt[J_LEN * MDIM];      // wv * invD  (separate buffer: must stay idempotent)
__device__ float g_heads[I_LEN * MDIM];
__device__ float g_m[NHEAD * J_LEN];      // column max of scaled logits
__device__ float g_invd[NHEAD * J_LEN];   // 1 / sum(exp(s - m))

// ---------------- fast exp on the FMA pipe (no MUFU) ----------------
// exp(x) = 2^(x*log2e); |rel err| ~ 2e-7 for x in [-87, ~1]
__device__ __forceinline__ float fexp(float x) {
    x = fmaxf(x, -87.0f);
    const float L2E = 1.4426950408889634f;
    float t  = __fmaf_rn(x, L2E, 12582912.0f);       // round-to-nearest-int trick
    int   n  = __float_as_int(t) - 0x4B400000;
    float fn = t - 12582912.0f;                      // == (float)n exactly
    float f  = __fmaf_rn(x, L2E, -fn);               // f = x*log2e - n, f in [-0.5, 0.5]
    // 2^f  (degree-6 Taylor in f with ln2 powers folded in)
    float p =            1.5403530393381609e-4f;
    p = __fmaf_rn(p, f, 1.3333558146428443e-3f);
    p = __fmaf_rn(p, f, 9.6181291076284770e-3f);
    p = __fmaf_rn(p, f, 5.5504108664821580e-2f);
    p = __fmaf_rn(p, f, 2.4022650695910070e-1f);
    p = __fmaf_rn(p, f, 6.9314718055994530e-1f);
    p = __fmaf_rn(p, f, 1.0f);
    return p * __int_as_float((n + 127) << 23);
}

// ---------------- SGEMM: C[2048x1024] = A[2048x1024(K)] @ B[1024x1024] ----------------
// 64x64 tile, BK=16, 16x16 threads, 4x4 microtile per thread.
#define GT 64
#define GK 16

__device__ __forceinline__ void sgemm_tile(const float* __restrict__ A,
                                           const float* __restrict__ B,
                                           float* __restrict__ C,
                                           int M, int N, int K) {
    __shared__ float As[GK][GT + 4];   // transposed A tile, padded (row = 272B, 16B aligned)
    __shared__ float Bs[GK][GT];

    int tx = threadIdx.x, ty = threadIdx.y;
    int tid = ty * 16 + tx;
    int m0 = blockIdx.y * GT;
    int n0 = blockIdx.x * GT;

    int arow = tid >> 2;            // 0..63
    int akk  = (tid & 3) * 4;       // 0,4,8,12
    int brow = tid >> 4;            // 0..15
    int bcol = (tid & 15) * 4;      // 0..60

    float acc[4][4] = {};

    for (int k0 = 0; k0 < K; k0 += GK) {
        float4 av = *(const float4*)&A[(m0 + arow) * K + k0 + akk];
        float4 bv = *(const float4*)&B[(k0 + brow) * N + n0 + bcol];
        As[akk + 0][arow] = av.x;
        As[akk + 1][arow] = av.y;
        As[akk + 2][arow] = av.z;
        As[akk + 3][arow] = av.w;
        *(float4*)&Bs[brow][bcol] = bv;
        __syncthreads();

        #pragma unroll
        for (int kk = 0; kk < GK; kk++) {
            float a4[4], b4[4];
            *(float4*)a4 = *(const float4*)&As[kk][ty * 4];
            *(float4*)b4 = *(const float4*)&Bs[kk][tx * 4];
            #pragma unroll
            for (int r = 0; r < 4; r++)
                #pragma unroll
                for (int c = 0; c < 4; c++)
                    acc[r][c] = __fmaf_rn(a4[r], b4[c], acc[r][c]);
        }
        __syncthreads();
    }

    #pragma unroll
    for (int r = 0; r < 4; r++) {
        float4 v = make_float4(acc[r][0], acc[r][1], acc[r][2], acc[r][3]);
        *(float4*)&C[(m0 + ty * 4 + r) * N + n0 + tx * 4] = v;
    }
}

// Three projection GEMMs in one launch (z selects which)
__global__ __launch_bounds__(256) void gemm3_kernel(const float* __restrict__ q,
                                                    const float* __restrict__ qw,
                                                    const float* __restrict__ k,
                                                    const float* __restrict__ kw,
                                                    const float* __restrict__ v,
                                                    const float* __restrict__ vw) {
    const float* A;
    const float* B;
    float* C;
    if (blockIdx.z == 0)      { A = q; B = qw; C = g_wq; }
    else if (blockIdx.z == 1) { A = k; B = kw; C = g_wk; }
    else                      { A = v; B = vw; C = g_wv; }
    sgemm_tile(A, B, C, I_LEN, MDIM, MDIM);
}

// Final projection: out = heads_flat @ o_w
__global__ __launch_bounds__(256) void gemm_out_kernel(const float* __restrict__ ow,
                                                       float* __restrict__ out) {
    sgemm_tile(g_heads, ow, out, I_LEN, MDIM, MDIM);
}

// ---------------- pass A: per-(h,j) column max + inv-sum-exp over i ----------------
// grid: (J/128, NHEAD), block 128. Thread owns one column j of head h.
__global__ __launch_bounds__(128) void stats_kernel() {
    int h = blockIdx.y;
    int j = blockIdx.x * 128 + threadIdx.x;
    int c0 = h * HD;

    float kreg[16];
    {
        const float* krow = &g_wk[j * MDIM + c0];
        #pragma unroll
        for (int k = 0; k < 16; k += 4) {
            float4 t = *(const float4*)&krow[k];
            kreg[k] = t.x; kreg[k + 1] = t.y; kreg[k + 2] = t.z; kreg[k + 3] = t.w;
        }
    }

    __shared__ float sq[128][20];   // 80B row stride: 16B aligned, low store conflicts

    float m = -1e30f;
    float D = 0.0f;

    for (int i0 = 0; i0 < I_LEN; i0 += 128) {
        __syncthreads();
        {
            int t = threadIdx.x;
            const float* qrow = &g_wq[(i0 + t) * MDIM + c0];
            #pragma unroll
            for (int k = 0; k < 16; k += 4)
                *(float4*)&sq[t][k] = *(const float4*)&qrow[k];
        }
        __syncthreads();

        #pragma unroll 4
        for (int ii = 0; ii < 128; ii++) {
            float s0 = 0.f, s1 = 0.f, s2 = 0.f, s3 = 0.f;
            #pragma unroll
            for (int k = 0; k < 16; k += 4) {
                s0 = __fmaf_rn(kreg[k    ], sq[ii][k    ], s0);
                s1 = __fmaf_rn(kreg[k + 1], sq[ii][k + 1], s1);
                s2 = __fmaf_rn(kreg[k + 2], sq[ii][k + 2], s2);
                s3 = __fmaf_rn(kreg[k + 3], sq[ii][k + 3], s3);
            }
            float s = ((s0 + s1) + (s2 + s3)) * 0.125f;   // exact scale by 1/sqrt(64)
            if (s <= m) {
                D += fexp(s - m);
            } else {
                D = __fmaf_rn(D, fexp(m - s), 1.0f);
                m = s;
            }
        }
    }

    g_m[h * J_LEN + j]    = m;
    g_invd[h * J_LEN + j] = 1.0f / D;
}

// ---------------- vt = wv * invD ----------------
__global__ __launch_bounds__(256) void vtilde_kernel() {
    int idx = blockIdx.x * 256 + threadIdx.x;      // over J_LEN*MDIM
    int j = idx >> 10;
    int c = idx & 1023;
    int h = c >> 4;
    g_vt[idx] = g_wv[idx] * g_invd[h * J_LEN + j];
}

// ---------------- pass B: heads[i,h,:] = sum_j exp(s-m) * vt[j,h,:] ----------------
// grid: (I/256, NHEAD), block 128; each thread owns 2 i-rows.
__global__ __launch_bounds__(128) void attn_kernel() {
    int h = blockIdx.y;
    int c0 = h * HD;
    int ia = blockIdx.x * 256 + threadIdx.x;
    int ib = ia + 128;

    float qa[16], qb[16], aa[16], ab[16];
    {
        const float* ra = &g_wq[ia * MDIM + c0];
        const float* rb = &g_wq[ib * MDIM + c0];
        #pragma unroll
        for (int k = 0; k < 16; k += 4) {
            float4 t = *(const float4*)&ra[k];
            qa[k] = t.x; qa[k + 1] = t.y; qa[k + 2] = t.z; qa[k + 3] = t.w;
            float4 u = *(const float4*)&rb[k];
            qb[k] = u.x; qb[k + 1] = u.y; qb[k + 2] = u.z; qb[k + 3] = u.w;
        }
    }
    #pragma unroll
    for (int v = 0; v < 16; v++) { aa[v] = 0.f; ab[v] = 0.f; }

    __shared__ float sk[128][20];
    __shared__ float sv[128][20];
    __shared__ float sm[128];

    for (int j0 = 0; j0 < J_LEN; j0 += 128) {
        __syncthreads();
        {
            int t = threadIdx.x;
            const float* krow = &g_wk[(j0 + t) * MDIM + c0];
            const float* vrow = &g_vt[(j0 + t) * MDIM + c0];
            #pragma unroll
            for (int k = 0; k < 16; k += 4) {
                *(float4*)&sk[t][k] = *(const float4*)&krow[k];
                *(float4*)&sv[t][k] = *(const float4*)&vrow[k];
            }
            sm[t] = g_m[h * J_LEN + j0 + t];
        }
        __syncthreads();

        #pragma unroll 2
        for (int jj = 0; jj < 128; jj++) {
            float s0 = 0.f, s1 = 0.f, s2 = 0.f, s3 = 0.f;
            float t0 = 0.f, t1 = 0.f, t2 = 0.f, t3 = 0.f;
            #pragma unroll
            for (int k = 0; k < 16; k += 4) {
                float k0 = sk[jj][k], k1 = sk[jj][k + 1], k2 = sk[jj][k + 2], k3 = sk[jj][k + 3];
                s0 = __fmaf_rn(k0, qa[k    ], s0);
                s1 = __fmaf_rn(k1, qa[k + 1], s1);
                s2 = __fmaf_rn(k2, qa[k + 2], s2);
                s3 = __fmaf_rn(k3, qa[k + 3], s3);
                t0 = __fmaf_rn(k0, qb[k    ], t0);
                t1 = __fmaf_rn(k1, qb[k + 1], t1);
                t2 = __fmaf_rn(k2, qb[k + 2], t2);
                t3 = __fmaf_rn(k3, qb[k + 3], t3);
            }
            // NOTE: same reduction tree + exact *0.125 as stats_kernel; dot uses
            // kreg*q in both (commuted operands are fine: FMA multiply is exact-symmetric)
            float sa = ((s0 + s1) + (s2 + s3)) * 0.125f;
            float sb = ((t0 + t1) + (t2 + t3)) * 0.125f;
            float mj = sm[jj];
            float ea = fexp(sa - mj);
            float eb = fexp(sb - mj);
            #pragma unroll
            for (int v = 0; v < 16; v++) {
                float vv = sv[jj][v];
                aa[v] = __fmaf_rn(ea, vv, aa[v]);
                ab[v] = __fmaf_rn(eb, vv, ab[v]);
            }
        }
    }

    {
        float* oa = &g_heads[ia * MDIM + c0];
        float* ob = &g_heads[ib * MDIM + c0];
        #pragma unroll
        for (int k = 0; k < 16; k += 4) {
            *(float4*)&oa[k] = make_float4(aa[k], aa[k + 1], aa[k + 2], aa[k + 3]);
            *(float4*)&ob[k] = make_float4(ab[k], ab[k + 1], ab[k + 2], ab[k + 3]);
        }
    }
}

// ---------------- launch ----------------
extern "C" void kernel_launch(void* const* d_in, const int* in_sizes, int n_in,
                              void* d_out, int out_size) {
    (void)in_sizes; (void)n_in; (void)out_size;
    const float* q  = (const float*)d_in[0];
    const float* k  = (const float*)d_in[1];
    const float* v  = (const float*)d_in[2];
    const float* qw = (const float*)d_in[3];
    const float* kw = (const float*)d_in[4];
    const float* vw = (const float*)d_in[5];
    const float* ow = (const float*)d_in[6];
    float* out = (float*)d_out;

    dim3 gblk(16, 16);
    dim3 ggrid3(MDIM / GT, I_LEN / GT, 3);
    gemm3_kernel<<<ggrid3, gblk>>>(q, qw, k, kw, v, vw);

    stats_kernel<<<dim3(J_LEN / 128, NHEAD), 128>>>();

    vtilde_kernel<<<(J_LEN * MDIM) / 256, 256>>>();

    attn_kernel<<<dim3(I_LEN / 256, NHEAD), 128>>>();

    gemm_out_kernel<<<dim3(MDIM / GT, I_LEN / GT), gblk>>>(ow, out);
}

// round 2
// speedup vs baseline: 1.1600x; 1.1600x over previous
#include <cuda_runtime.h>

// Problem constants
#define I_LEN 2048
#define J_LEN 2048
#define MDIM  1024
#define NHEAD 64     // "head" axis (weights dim1)
#define HD    16     // per-head contracted feature dim (weights dim2)

// combined scale: (1/sqrt(64)) * log2(e)  -- logits kept in log2 domain
#define CSCALE 0.18033688011112042f

// ---------------- scratch (static device globals; no allocation) ----------------
__device__ float g_wq[I_LEN * MDIM];
__device__ float g_wk[J_LEN * MDIM];
__device__ float g_wv[J_LEN * MDIM];
__device__ float g_vt[J_LEN * MDIM];      // wv * invD (written by stats; idempotent)
__device__ float g_heads[I_LEN * MDIM];
__device__ float g_m[NHEAD * J_LEN];      // column max of log2-scaled logits

// ---------------- exp2 on the MUFU pipe (frees FMA issue slots) ----------------
__device__ __forceinline__ float fexp2(float x) {
    float y;
    asm("ex2.approx.ftz.f32 %0, %1;" : "=f"(y) : "f"(x));
    return y;
}

// ---------------- SGEMM: C[2048x1024] = A[2048x1024(K)] @ B[1024x1024] ----------------
// 64x64 tile, BK=16, 16x16 threads, 4x4 microtile per thread. (unchanged this round)
#define GT 64
#define GK 16

__device__ __forceinline__ void sgemm_tile(const float* __restrict__ A,
                                           const float* __restrict__ B,
                                           float* __restrict__ C,
                                           int M, int N, int K) {
    __shared__ float As[GK][GT + 4];   // transposed A tile, padded
    __shared__ float Bs[GK][GT];

    int tx = threadIdx.x, ty = threadIdx.y;
    int tid = ty * 16 + tx;
    int m0 = blockIdx.y * GT;
    int n0 = blockIdx.x * GT;

    int arow = tid >> 2;            // 0..63
    int akk  = (tid & 3) * 4;       // 0,4,8,12
    int brow = tid >> 4;            // 0..15
    int bcol = (tid & 15) * 4;      // 0..60

    float acc[4][4] = {};

    for (int k0 = 0; k0 < K; k0 += GK) {
        float4 av = *(const float4*)&A[(m0 + arow) * K + k0 + akk];
        float4 bv = *(const float4*)&B[(k0 + brow) * N + n0 + bcol];
        As[akk + 0][arow] = av.x;
        As[akk + 1][arow] = av.y;
        As[akk + 2][arow] = av.z;
        As[akk + 3][arow] = av.w;
        *(float4*)&Bs[brow][bcol] = bv;
        __syncthreads();

        #pragma unroll
        for (int kk = 0; kk < GK; kk++) {
            float a4[4], b4[4];
            *(float4*)a4 = *(const float4*)&As[kk][ty * 4];
            *(float4*)b4 = *(const float4*)&Bs[kk][tx * 4];
            #pragma unroll
            for (int r = 0; r < 4; r++)
                #pragma unroll
                for (int c = 0; c < 4; c++)
                    acc[r][c] = __fmaf_rn(a4[r], b4[c], acc[r][c]);
        }
        __syncthreads();
    }

    #pragma unroll
    for (int r = 0; r < 4; r++) {
        float4 v = make_float4(acc[r][0], acc[r][1], acc[r][2], acc[r][3]);
        *(float4*)&C[(m0 + ty * 4 + r) * N + n0 + tx * 4] = v;
    }
}

__global__ __launch_bounds__(256) void gemm3_kernel(const float* __restrict__ q,
                                                    const float* __restrict__ qw,
                                                    const float* __restrict__ k,
                                                    const float* __restrict__ kw,
                                                    const float* __restrict__ v,
                                                    const float* __restrict__ vw) {
    const float* A;
    const float* B;
    float* C;
    if (blockIdx.z == 0)      { A = q; B = qw; C = g_wq; }
    else if (blockIdx.z == 1) { A = k; B = kw; C = g_wk; }
    else                      { A = v; B = vw; C = g_wv; }
    sgemm_tile(A, B, C, I_LEN, MDIM, MDIM);
}

__global__ __launch_bounds__(256) void gemm_out_kernel(const float* __restrict__ ow,
                                                       float* __restrict__ out) {
    sgemm_tile(g_heads, ow, out, I_LEN, MDIM, MDIM);
}

// ---------------- pass A: per-(h,j) column stats over i, fused vt = wv/D ----------------
// grid: (J/128, NHEAD), block 128. Thread owns one column j of head h.
// Branch-free online softmax in log2 domain; exp2 on MUFU.
__global__ __launch_bounds__(128) void stats_kernel() {
    int h = blockIdx.y;
    int j = blockIdx.x * 128 + threadIdx.x;
    int c0 = h * HD;

    float kreg[16];
    {
        const float* krow = &g_wk[j * MDIM + c0];
        #pragma unroll
        for (int k = 0; k < 16; k += 4) {
            float4 t = *(const float4*)&krow[k];
            kreg[k] = t.x; kreg[k + 1] = t.y; kreg[k + 2] = t.z; kreg[k + 3] = t.w;
        }
    }

    __shared__ float sq[128][20];   // 80B row stride (16B aligned)

    float m = -1e30f;
    float D = 0.0f;

    for (int i0 = 0; i0 < I_LEN; i0 += 128) {
        __syncthreads();
        {
            int t = threadIdx.x;
            const float* qrow = &g_wq[(i0 + t) * MDIM + c0];
            #pragma unroll
            for (int k = 0; k < 16; k += 4)
                *(float4*)&sq[t][k] = *(const float4*)&qrow[k];
        }
        __syncthreads();

        #pragma unroll 4
        for (int ii = 0; ii < 128; ii++) {
            float s0 = 0.f, s1 = 0.f, s2 = 0.f, s3 = 0.f;
            #pragma unroll
            for (int k = 0; k < 16; k += 4) {
                s0 = __fmaf_rn(kreg[k    ], sq[ii][k    ], s0);
                s1 = __fmaf_rn(kreg[k + 1], sq[ii][k + 1], s1);
                s2 = __fmaf_rn(kreg[k + 2], sq[ii][k + 2], s2);
                s3 = __fmaf_rn(kreg[k + 3], sq[ii][k + 3], s3);
            }
            float s = ((s0 + s1) + (s2 + s3)) * CSCALE;   // log2-domain logit
            // branch-free online update; ex2(0)==1.0 exactly on the common path
            float mn = fmaxf(m, s);
            float e_old = fexp2(m - mn);
            float e_new = fexp2(s - mn);
            D = __fmaf_rn(D, e_old, e_new);
            m = mn;
        }
    }

    float invd = 1.0f / D;
    g_m[h * J_LEN + j] = m;

    // fused vtilde: vt[j,h,:] = wv[j,h,:] * invd
    {
        const float* vr  = &g_wv[j * MDIM + c0];
        float*       vtr = &g_vt[j * MDIM + c0];
        #pragma unroll
        for (int k = 0; k < 16; k += 4) {
            float4 t = *(const float4*)&vr[k];
            t.x *= invd; t.y *= invd; t.z *= invd; t.w *= invd;
            *(float4*)&vtr[k] = t;
        }
    }
}

// ---------------- pass B: heads[i,h,:] = sum_j 2^(s-m) * vt[j,h,:] ----------------
// grid: (I/256, NHEAD), block 128; each thread owns 2 i-rows.
__global__ __launch_bounds__(128) void attn_kernel() {
    int h = blockIdx.y;
    int c0 = h * HD;
    int ia = blockIdx.x * 256 + threadIdx.x;
    int ib = ia + 128;

    float qa[16], qb[16], aa[16], ab[16];
    {
        const float* ra = &g_wq[ia * MDIM + c0];
        const float* rb = &g_wq[ib * MDIM + c0];
        #pragma unroll
        for (int k = 0; k < 16; k += 4) {
            float4 t = *(const float4*)&ra[k];
            qa[k] = t.x; qa[k + 1] = t.y; qa[k + 2] = t.z; qa[k + 3] = t.w;
            float4 u = *(const float4*)&rb[k];
            qb[k] = u.x; qb[k + 1] = u.y; qb[k + 2] = u.z; qb[k + 3] = u.w;
        }
    }
    #pragma unroll
    for (int v = 0; v < 16; v++) { aa[v] = 0.f; ab[v] = 0.f; }

    __shared__ float sk[128][20];
    __shared__ float sv[128][20];
    __shared__ float sm[128];

    for (int j0 = 0; j0 < J_LEN; j0 += 128) {
        __syncthreads();
        {
            int t = threadIdx.x;
            const float* krow = &g_wk[(j0 + t) * MDIM + c0];
            const float* vrow = &g_vt[(j0 + t) * MDIM + c0];
            #pragma unroll
            for (int k = 0; k < 16; k += 4) {
                *(float4*)&sk[t][k] = *(const float4*)&krow[k];
                *(float4*)&sv[t][k] = *(const float4*)&vrow[k];
            }
            sm[t] = g_m[h * J_LEN + j0 + t];
        }
        __syncthreads();

        #pragma unroll 2
        for (int jj = 0; jj < 128; jj++) {
            float s0 = 0.f, s1 = 0.f, s2 = 0.f, s3 = 0.f;
            float t0 = 0.f, t1 = 0.f, t2 = 0.f, t3 = 0.f;
            #pragma unroll
            for (int k = 0; k < 16; k += 4) {
                float k0 = sk[jj][k], k1 = sk[jj][k + 1], k2 = sk[jj][k + 2], k3 = sk[jj][k + 3];
                s0 = __fmaf_rn(k0, qa[k    ], s0);
                s1 = __fmaf_rn(k1, qa[k + 1], s1);
                s2 = __fmaf_rn(k2, qa[k + 2], s2);
                s3 = __fmaf_rn(k3, qa[k + 3], s3);
                t0 = __fmaf_rn(k0, qb[k    ], t0);
                t1 = __fmaf_rn(k1, qb[k + 1], t1);
                t2 = __fmaf_rn(k2, qb[k + 2], t2);
                t3 = __fmaf_rn(k3, qb[k + 3], t3);
            }
            // same dot accumulation tree as stats_kernel; scale+sub fused into one FMA
            float sa = ((s0 + s1) + (s2 + s3));
            float sb = ((t0 + t1) + (t2 + t3));
            float mj = sm[jj];
            float ea = fexp2(__fmaf_rn(sa, CSCALE, -mj));
            float eb = fexp2(__fmaf_rn(sb, CSCALE, -mj));
            #pragma unroll
            for (int v = 0; v < 16; v++) {
                float vv = sv[jj][v];
                aa[v] = __fmaf_rn(ea, vv, aa[v]);
                ab[v] = __fmaf_rn(eb, vv, ab[v]);
            }
        }
    }

    {
        float* oa = &g_heads[ia * MDIM + c0];
        float* ob = &g_heads[ib * MDIM + c0];
        #pragma unroll
        for (int k = 0; k < 16; k += 4) {
            *(float4*)&oa[k] = make_float4(aa[k], aa[k + 1], aa[k + 2], aa[k + 3]);
            *(float4*)&ob[k] = make_float4(ab[k], ab[k + 1], ab[k + 2], ab[k + 3]);
        }
    }
}

// ---------------- launch ----------------
extern "C" void kernel_launch(void* const* d_in, const int* in_sizes, int n_in,
                              void* d_out, int out_size) {
    (void)in_sizes; (void)n_in; (void)out_size;
    const float* q  = (const float*)d_in[0];
    const float* k  = (const float*)d_in[1];
    const float* v  = (const float*)d_in[2];
    const float* qw = (const float*)d_in[3];
    const float* kw = (const float*)d_in[4];
    const float* vw = (const float*)d_in[5];
    const float* ow = (const float*)d_in[6];
    float* out = (float*)d_out;

    dim3 gblk(16, 16);
    dim3 ggrid3(MDIM / GT, I_LEN / GT, 3);
    gemm3_kernel<<<ggrid3, gblk>>>(q, qw, k, kw, v, vw);

    stats_kernel<<<dim3(J_LEN / 128, NHEAD), 128>>>();

    attn_kernel<<<dim3(I_LEN / 256, NHEAD), 128>>>();

    gemm_out_kernel<<<dim3(MDIM / GT, I_LEN / GT), gblk>>>(ow, out);
}

// round 4
// speedup vs baseline: 1.2012x; 1.0355x over previous
#include <cuda_runtime.h>

// Problem constants
#define I_LEN 2048
#define J_LEN 2048
#define MDIM  1024
#define NHEAD 64     // "head" axis (weights dim1)
#define HD    16     // per-head contracted feature dim (weights dim2)

// combined scale: (1/sqrt(64)) * log2(e)  -- logits kept in log2 domain
#define CSCALE 0.18033688011112042f

typedef unsigned long long u64;

// ---------------- scratch (static device globals; no allocation) ----------------
__device__ float g_wq[I_LEN * MDIM];
__device__ float g_wk[J_LEN * MDIM];
__device__ float g_wv[J_LEN * MDIM];
__device__ float g_vt[J_LEN * MDIM];      // wv * invD (written by stats; idempotent)
__device__ float g_heads[I_LEN * MDIM];
__device__ float g_m[NHEAD * J_LEN];      // column max of log2-scaled logits

// ---------------- packed fp32x2 FMA (Blackwell sm_100+) ----------------
__device__ __forceinline__ u64 ffma2(u64 a, u64 b, u64 c) {
    u64 d;
    asm("fma.rn.f32x2 %0, %1, %2, %3;" : "=l"(d) : "l"(a), "l"(b), "l"(c));
    return d;
}
__device__ __forceinline__ u64 fdup(float x) {
    u64 d;
    asm("mov.b64 %0, {%1, %1};" : "=l"(d) : "f"(x));
    return d;
}
__device__ __forceinline__ float2 funpack(u64 p) {
    float2 r;
    asm("mov.b64 {%0, %1}, %2;" : "=f"(r.x), "=f"(r.y) : "l"(p));
    return r;
}

// ---------------- exp2 on the MUFU pipe ----------------
__device__ __forceinline__ float fexp2(float x) {
    float y;
    asm("ex2.approx.ftz.f32 %0, %1;" : "=f"(y) : "f"(x));
    return y;
}

// ---------------- SGEMM: C[2048x1024] = A[2048xK] @ B[Kx1024], K=1024 ----------------
// 128x128 tile, BK=8, 256 threads, 8x8 microtile per thread, FFMA2 inner product.
// A held in smem pre-duplicated ({a,a} pairs): As[k][2m] = As[k][2m+1] = A[m,k].
#define GBM 128
#define GBN 128
#define GBK 8
#define GNK (MDIM / GBK)

__device__ __forceinline__ void sgemm_tile(const float* __restrict__ A,
                                           const float* __restrict__ B,
                                           float* __restrict__ C,
                                           int N, int K) {
    __shared__ float As[2][GBK][2 * GBM];   // duplicated pairs
    __shared__ float Bs[2][GBK][GBN];

    int tid = threadIdx.x;
    int m0 = blockIdx.y * GBM;
    int n0 = blockIdx.x * GBN;

    int arow = tid >> 1;            // 0..127
    int acol = (tid & 1) * 4;       // 0 or 4
    int brow = tid >> 5;            // 0..7
    int bcol = (tid & 31) * 4;      // 0..124

    int tx = tid & 15;              // n-block
    int ty = tid >> 4;              // m-block

    const float* Aptr = A + (m0 + arow) * K + acol;
    const float* Bptr = B + brow * N + n0 + bcol;

    u64 acc[8][4];
    #pragma unroll
    for (int r = 0; r < 8; r++)
        #pragma unroll
        for (int c = 0; c < 4; c++) acc[r][c] = 0ull;

    float4 av = *(const float4*)Aptr;
    float4 bv = *(const float4*)Bptr;

    // store tile 0
    *(u64*)&As[0][acol + 0][2 * arow] = fdup(av.x);
    *(u64*)&As[0][acol + 1][2 * arow] = fdup(av.y);
    *(u64*)&As[0][acol + 2][2 * arow] = fdup(av.z);
    *(u64*)&As[0][acol + 3][2 * arow] = fdup(av.w);
    *(float4*)&Bs[0][brow][bcol] = bv;
    __syncthreads();

    for (int t = 0; t < GNK; t++) {
        int buf = t & 1;
        if (t + 1 < GNK) {
            av = *(const float4*)(Aptr + (t + 1) * GBK);
            bv = *(const float4*)(Bptr + (size_t)(t + 1) * GBK * N);
        }

        #pragma unroll
        for (int kk = 0; kk < GBK; kk++) {
            // pair for m-row m lives at float index 2m:
            //   first half  m = ty*4 + r      -> index ty*8 + ...
            //   second half m = 64 + ty*4 + r -> index 128 + ty*8 + ...
            ulonglong2 a01 = *(const ulonglong2*)&As[buf][kk][ty * 8];
            ulonglong2 a23 = *(const ulonglong2*)&As[buf][kk][ty * 8 + 4];
            ulonglong2 a45 = *(const ulonglong2*)&As[buf][kk][128 + ty * 8];
            ulonglong2 a67 = *(const ulonglong2*)&As[buf][kk][128 + ty * 8 + 4];
            ulonglong2 b01 = *(const ulonglong2*)&Bs[buf][kk][tx * 4];
            ulonglong2 b23 = *(const ulonglong2*)&Bs[buf][kk][64 + tx * 4];

            u64 ar[8] = { a01.x, a01.y, a23.x, a23.y, a45.x, a45.y, a67.x, a67.y };
            #pragma unroll
            for (int r = 0; r < 8; r++) {
                acc[r][0] = ffma2(ar[r], b01.x, acc[r][0]);
                acc[r][1] = ffma2(ar[r], b01.y, acc[r][1]);
                acc[r][2] = ffma2(ar[r], b23.x, acc[r][2]);
                acc[r][3] = ffma2(ar[r], b23.y, acc[r][3]);
            }
        }

        if (t + 1 < GNK) {
            int nb = buf ^ 1;
            *(u64*)&As[nb][acol + 0][2 * arow] = fdup(av.x);
            *(u64*)&As[nb][acol + 1][2 * arow] = fdup(av.y);
            *(u64*)&As[nb][acol + 2][2 * arow] = fdup(av.z);
            *(u64*)&As[nb][acol + 3][2 * arow] = fdup(av.w);
            *(float4*)&Bs[nb][brow][bcol] = bv;
        }
        __syncthreads();
    }

    #pragma unroll
    for (int r = 0; r < 8; r++) {
        int row = (r < 4) ? (m0 + ty * 4 + r) : (m0 + 64 + ty * 4 + (r - 4));
        float2 c0 = funpack(acc[r][0]);
        float2 c1 = funpack(acc[r][1]);
        float2 c2 = funpack(acc[r][2]);
        float2 c3 = funpack(acc[r][3]);
        *(float4*)&C[row * N + n0 + tx * 4]      = make_float4(c0.x, c0.y, c1.x, c1.y);
        *(float4*)&C[row * N + n0 + 64 + tx * 4] = make_float4(c2.x, c2.y, c3.x, c3.y);
    }
}

__global__ __launch_bounds__(256) void gemm3_kernel(const float* __restrict__ q,
                                                    const float* __restrict__ qw,
                                                    const float* __restrict__ k,
                                                    const float* __restrict__ kw,
                                                    const float* __restrict__ v,
                                                    const float* __restrict__ vw) {
    const float* A;
    const float* B;
    float* C;
    if (blockIdx.z == 0)      { A = q; B = qw; C = g_wq; }
    else if (blockIdx.z == 1) { A = k; B = kw; C = g_wk; }
    else                      { A = v; B = vw; C = g_wv; }
    sgemm_tile(A, B, C, MDIM, MDIM);
}

__global__ __launch_bounds__(256) void gemm_out_kernel(const float* __restrict__ ow,
                                                       float* __restrict__ out) {
    sgemm_tile(g_heads, ow, out, MDIM, MDIM);
}

// ---------------- pass A: per-(h,j) column stats over i, fused vt = wv/D ----------------
// grid: (J/128, NHEAD), block 128. Thread owns one column j of head h.
// Dot via FFMA2 pairs; partial tree identical to attn_kernel: ((s0+s1)+(s2+s3)).
__global__ __launch_bounds__(128) void stats_kernel() {
    int h = blockIdx.y;
    int j = blockIdx.x * 128 + threadIdx.x;
    int c0 = h * HD;

    u64 kp[8];     // 16 k-values as 8 pairs
    {
        const ulonglong2* krow = (const ulonglong2*)&g_wk[j * MDIM + c0];
        #pragma unroll
        for (int k = 0; k < 4; k++) {
            ulonglong2 t = krow[k];
            kp[2 * k] = t.x; kp[2 * k + 1] = t.y;
        }
    }

    __shared__ float sq[128][20];   // 80B row stride (16B aligned)

    float m = -1e30f;
    float D = 0.0f;

    for (int i0 = 0; i0 < I_LEN; i0 += 128) {
        __syncthreads();
        {
            int t = threadIdx.x;
            const float* qrow = &g_wq[(i0 + t) * MDIM + c0];
            #pragma unroll
            for (int k = 0; k < 16; k += 4)
                *(float4*)&sq[t][k] = *(const float4*)&qrow[k];
        }
        __syncthreads();

        #pragma unroll 4
        for (int ii = 0; ii < 128; ii++) {
            ulonglong2 q01 = *(const ulonglong2*)&sq[ii][0];
            ulonglong2 q23 = *(const ulonglong2*)&sq[ii][4];
            ulonglong2 q45 = *(const ulonglong2*)&sq[ii][8];
            ulonglong2 q67 = *(const ulonglong2*)&sq[ii][12];
            u64 pA = 0ull, pB = 0ull;        // pA lanes: s0,s1 ; pB lanes: s2,s3
            pA = ffma2(kp[0], q01.x, pA);  pB = ffma2(kp[1], q01.y, pB);
            pA = ffma2(kp[2], q23.x, pA);  pB = ffma2(kp[3], q23.y, pB);
            pA = ffma2(kp[4], q45.x, pA);  pB = ffma2(kp[5], q45.y, pB);
            pA = ffma2(kp[6], q67.x, pA);  pB = ffma2(kp[7], q67.y, pB);
            float2 fa = funpack(pA);
            float2 fb = funpack(pB);
            float s = ((fa.x + fa.y) + (fb.x + fb.y)) * CSCALE;   // log2-domain logit
            // branch-free online update; ex2(0)==1.0 exactly on the common path
            float mn = fmaxf(m, s);
            float e_old = fexp2(m - mn);
            float e_new = fexp2(s - mn);
            D = __fmaf_rn(D, e_old, e_new);
            m = mn;
        }
    }

    float invd = 1.0f / D;
    g_m[h * J_LEN + j] = m;

    // fused vtilde: vt[j,h,:] = wv[j,h,:] * invd
    {
        const float* vr  = &g_wv[j * MDIM + c0];
        float*       vtr = &g_vt[j * MDIM + c0];
        #pragma unroll
        for (int k = 0; k < 16; k += 4) {
            float4 t = *(const float4*)&vr[k];
            t.x *= invd; t.y *= invd; t.z *= invd; t.w *= invd;
            *(float4*)&vtr[k] = t;
        }
    }
}

// ---------------- pass B: heads[i,h,:] = sum_j 2^(s-m) * vt[j,h,:] ----------------
// grid: (I/256, NHEAD), block 128; each thread owns 2 i-rows. FFMA2 everywhere.
__global__ __launch_bounds__(128) void attn_kernel() {
    int h = blockIdx.y;
    int c0 = h * HD;
    int ia = blockIdx.x * 256 + threadIdx.x;
    int ib = ia + 128;

    u64 qa[8], qb[8], aa[8], ab[8];
    {
        const ulonglong2* ra = (const ulonglong2*)&g_wq[ia * MDIM + c0];
        const ulonglong2* rb = (const ulonglong2*)&g_wq[ib * MDIM + c0];
        #pragma unroll
        for (int k = 0; k < 4; k++) {
            ulonglong2 t = ra[k];
            qa[2 * k] = t.x; qa[2 * k + 1] = t.y;
            ulonglong2 u = rb[k];
            qb[2 * k] = u.x; qb[2 * k + 1] = u.y;
        }
    }
    #pragma unroll
    for (int v = 0; v < 8; v++) { aa[v] = 0ull; ab[v] = 0ull; }

    __shared__ float sk[128][20];
    __shared__ float sv[128][20];
    __shared__ float sm[128];

    for (int j0 = 0; j0 < J_LEN; j0 += 128) {
        __syncthreads();
        {
            int t = threadIdx.x;
            const float* krow = &g_wk[(j0 + t) * MDIM + c0];
            const float* vrow = &g_vt[(j0 + t) * MDIM + c0];
            #pragma unroll
            for (int k = 0; k < 16; k += 4) {
                *(float4*)&sk[t][k] = *(const float4*)&krow[k];
                *(float4*)&sv[t][k] = *(const float4*)&vrow[k];
            }
            sm[t] = g_m[h * J_LEN + j0 + t];
        }
        __syncthreads();

        #pragma unroll 2
        for (int jj = 0; jj < 128; jj++) {
            ulonglong2 k01 = *(const ulonglong2*)&sk[jj][0];
            ulonglong2 k23 = *(const ulonglong2*)&sk[jj][4];
            ulonglong2 k45 = *(const ulonglong2*)&sk[jj][8];
            ulonglong2 k67 = *(const ulonglong2*)&sk[jj][12];

            u64 pAa = 0ull, pBa = 0ull, pAb = 0ull, pBb = 0ull;
            pAa = ffma2(k01.x, qa[0], pAa);  pBa = ffma2(k01.y, qa[1], pBa);
            pAb = ffma2(k01.x, qb[0], pAb);  pBb = ffma2(k01.y, qb[1], pBb);
            pAa = ffma2(k23.x, qa[2], pAa);  pBa = ffma2(k23.y, qa[3], pBa);
            pAb = ffma2(k23.x, qb[2], pAb);  pBb = ffma2(k23.y, qb[3], pBb);
            pAa = ffma2(k45.x, qa[4], pAa);  pBa = ffma2(k45.y, qa[5], pBa);
            pAb = ffma2(k45.x, qb[4], pAb);  pBb = ffma2(k45.y, qb[5], pBb);
            pAa = ffma2(k67.x, qa[6], pAa);  pBa = ffma2(k67.y, qa[7], pBa);
            pAb = ffma2(k67.x, qb[6], pAb);  pBb = ffma2(k67.y, qb[7], pBb);

            float2 a1 = funpack(pAa), a2 = funpack(pBa);
            float2 b1 = funpack(pAb), b2 = funpack(pBb);
            float sa = (a1.x + a1.y) + (a2.x + a2.y);   // same tree as stats
            float sb = (b1.x + b1.y) + (b2.x + b2.y);
            float mj = sm[jj];
            float ea = fexp2(__fmaf_rn(sa, CSCALE, -mj));
            float eb = fexp2(__fmaf_rn(sb, CSCALE, -mj));
            u64 ed = fdup(ea);
            u64 fd = fdup(eb);

            ulonglong2 v01 = *(const ulonglong2*)&sv[jj][0];
            ulonglong2 v23 = *(const ulonglong2*)&sv[jj][4];
            ulonglong2 v45 = *(const ulonglong2*)&sv[jj][8];
            ulonglong2 v67 = *(const ulonglong2*)&sv[jj][12];
            u64 vr[8] = { v01.x, v01.y, v23.x, v23.y, v45.x, v45.y, v67.x, v67.y };
            #pragma unroll
            for (int v = 0; v < 8; v++) {
                aa[v] = ffma2(ed, vr[v], aa[v]);
                ab[v] = ffma2(fd, vr[v], ab[v]);
            }
        }
    }

    {
        float* oa = &g_heads[ia * MDIM + c0];
        float* ob = &g_heads[ib * MDIM + c0];
        #pragma unroll
        for (int k = 0; k < 4; k++) {
            float2 p0 = funpack(aa[2 * k]);
            float2 p1 = funpack(aa[2 * k + 1]);
            *(float4*)&oa[4 * k] = make_float4(p0.x, p0.y, p1.x, p1.y);
            float2 r0 = funpack(ab[2 * k]);
            float2 r1 = funpack(ab[2 * k + 1]);
            *(float4*)&ob[4 * k] = make_float4(r0.x, r0.y, r1.x, r1.y);
        }
    }
}

// ---------------- launch ----------------
extern "C" void kernel_launch(void* const* d_in, const int* in_sizes, int n_in,
                              void* d_out, int out_size) {
    (void)in_sizes; (void)n_in; (void)out_size;
    const float* q  = (const float*)d_in[0];
    const float* k  = (const float*)d_in[1];
    const float* v  = (const float*)d_in[2];
    const float* qw = (const float*)d_in[3];
    const float* kw = (const float*)d_in[4];
    const float* vw = (const float*)d_in[5];
    const float* ow = (const float*)d_in[6];
    float* out = (float*)d_out;

    dim3 ggrid3(MDIM / GBN, I_LEN / GBM, 3);
    gemm3_kernel<<<ggrid3, 256>>>(q, qw, k, kw, v, vw);

    stats_kernel<<<dim3(J_LEN / 128, NHEAD), 128>>>();

    attn_kernel<<<dim3(I_LEN / 256, NHEAD), 128>>>();

    gemm_out_kernel<<<dim3(MDIM / GBN, I_LEN / GBM), 256>>>(ow, out);
}